// round 5
// baseline (speedup 1.0000x reference)
#include <cuda_runtime.h>
#include <math.h>

#define BB 32
#define EE 512
#define HH 1024
#define VV 32000
#define TT 64
#define START_TOK 1
#define F32_TINY 1.17549435e-38f
#define KC 32
#define TILEV 128
#define NCHUNK_LOG (HH / KC)     // 16
#define KTOT 1536
#define SPLITK 4
#define KSEG (KTOT / SPLITK)     // 384
#define NCHUNK_LSTM (KSEG / KC)  // 12
#define WS_STRIDE 36
#define NTILE 32                 // j-tiles of 32 hidden units

// ---------------- device scratch ----------------
__device__ __align__(16) float g_xhA[KTOT * BB]; // [k][b]: x(512) then h(1024)
__device__ __align__(16) float g_xhB[KTOT * BB];
__device__ __align__(16) float g_c[HH * BB];
__device__ __align__(16) float g_acc[NTILE * 128 * BB]; // per-tile gate accum
__device__ int g_cnt[NTILE];
__device__ unsigned long long g_best[TT * BB];
__device__ __align__(16) float g_stage[(size_t)BB * TT * VV]; // [b][t][v]

// ---------------- f32x2 packed math ----------------
__device__ __forceinline__ unsigned long long pack2(float lo, float hi) {
    unsigned long long r;
    asm("mov.b64 %0, {%1, %2};" : "=l"(r) : "f"(lo), "f"(hi));
    return r;
}
__device__ __forceinline__ void unpack2(unsigned long long v, float& lo, float& hi) {
    asm("mov.b64 {%0, %1}, %2;" : "=f"(lo), "=f"(hi) : "l"(v));
}
__device__ __forceinline__ unsigned long long fma2(unsigned long long a,
                                                   unsigned long long b,
                                                   unsigned long long c) {
    unsigned long long d;
    asm("fma.rn.f32x2 %0, %1, %2, %3;" : "=l"(d) : "l"(a), "l"(b), "l"(c));
    return d;
}

// ---------------- threefry2x32 (JAX-compatible) ----------------
__device__ __forceinline__ void threefry2x32_dev(unsigned k0, unsigned k1,
                                                 unsigned x0, unsigned x1,
                                                 unsigned& o0, unsigned& o1) {
    unsigned ks2 = k0 ^ k1 ^ 0x1BD11BDAu;
    x0 += k0; x1 += k1;
#define TF_RND(r) { x0 += x1; x1 = __funnelshift_l(x1, x1, r); x1 ^= x0; }
    TF_RND(13) TF_RND(15) TF_RND(26) TF_RND(6)  x0 += k1;  x1 += ks2 + 1u;
    TF_RND(17) TF_RND(29) TF_RND(16) TF_RND(24) x0 += ks2; x1 += k0 + 2u;
    TF_RND(13) TF_RND(15) TF_RND(26) TF_RND(6)  x0 += k0;  x1 += k1 + 3u;
    TF_RND(17) TF_RND(29) TF_RND(16) TF_RND(24) x0 += k1;  x1 += ks2 + 4u;
    TF_RND(13) TF_RND(15) TF_RND(26) TF_RND(6)  x0 += ks2; x1 += k0 + 5u;
#undef TF_RND
    o0 = x0; o1 = x1;
}

__device__ __forceinline__ unsigned ford(float f) {
    unsigned u = __float_as_uint(f);
    return (u & 0x80000000u) ? ~u : (u | 0x80000000u);
}
__device__ __forceinline__ unsigned long long u64max(unsigned long long a,
                                                     unsigned long long b) {
    return a > b ? a : b;
}
__device__ __forceinline__ int decode_tok(unsigned long long key) {
    return (int)(0xFFFFFFFFu - (unsigned)(key & 0xFFFFFFFFull));
}

// ---------------- cp.async helpers ----------------
__device__ __forceinline__ void cp_async16(unsigned dst, const void* src) {
    asm volatile("cp.async.cg.shared.global [%0], [%1], 16;"
                 :: "r"(dst), "l"(src) : "memory");
}
__device__ __forceinline__ void cp_commit() {
    asm volatile("cp.async.commit_group;" ::: "memory");
}

// ---------------- K0: h0/c0 from condition; clear flags ----------------
__global__ __launch_bounds__(256) void init_kernel(
    const float* __restrict__ cond, const float* __restrict__ Wh,
    const float* __restrict__ bh,   const float* __restrict__ Wc,
    const float* __restrict__ bc,
    float* __restrict__ hout, float* __restrict__ cout) {
    int j = blockIdx.x * 8 + (threadIdx.x >> 5);
    int lane = threadIdx.x & 31;
    if (blockIdx.x < 8) {
        int idx = blockIdx.x * 256 + threadIdx.x;
        if (idx < TT * BB) g_best[idx] = 0ull;
        if (idx < NTILE) g_cnt[idx] = 0;
    }
    const float* cr = cond + (size_t)lane * EE;
    const float* wh = Wh + (size_t)j * EE;
    const float* wc = Wc + (size_t)j * EE;
    float ah = bh[j], ac = bc[j];
#pragma unroll 4
    for (int k = 0; k < EE; k += 4) {
        float4 c4 = *(const float4*)(cr + k);
        float4 h4 = *(const float4*)(wh + k);
        float4 q4 = *(const float4*)(wc + k);
        ah = fmaf(c4.x, h4.x, ah); ah = fmaf(c4.y, h4.y, ah);
        ah = fmaf(c4.z, h4.z, ah); ah = fmaf(c4.w, h4.w, ah);
        ac = fmaf(c4.x, q4.x, ac); ac = fmaf(c4.y, q4.y, ac);
        ac = fmaf(c4.z, q4.z, ac); ac = fmaf(c4.w, q4.w, ac);
    }
    hout[j * BB + lane] = ah;
    cout[j * BB + lane] = ac;
}

// ---------------- K-gather: x part only -> xh_r[k][b] ----------------
__global__ __launch_bounds__(256) void gather_kernel(
    const float* __restrict__ embed, float* __restrict__ xh_r, int t) {
    int idx = blockIdx.x * 256 + threadIdx.x;  // 0..16383
    int b = idx & 31;
    int k = idx >> 5;
    int tok = START_TOK;
    if (t > 0) tok = decode_tok(g_best[(t - 1) * BB + b]);
    xh_r[k * BB + b] = embed[(size_t)tok * EE + k];
}

// ---------------- K1: fused LSTM GEMM + split-K reduce + cell ----------------
// grid (NTILE, SPLITK). Tile covers rows {g*HH + j0 + jl : g in 0..3, jl 0..31}.
// 256 threads: rt=tid&31 (jl), bt=tid>>5; rj = gate. Thread ends owning
// all 4 gates of one j for 4 b's -> computes cell inline (seg 3).
__global__ __launch_bounds__(256) void lstm_kernel(
    const float* __restrict__ Wih, const float* __restrict__ Whh,
    const float* __restrict__ bih, const float* __restrict__ bhh,
    const float* __restrict__ xh_r, float* __restrict__ xh_w,
    float* __restrict__ cbuf) {
    __shared__ __align__(16) float Ws[2][128][WS_STRIDE];
    __shared__ __align__(16) float xs[2][KC][BB];
    int tid = threadIdx.x;
    int rt = tid & 31;
    int bt = tid >> 5;
    int tile = blockIdx.x;
    int seg = blockIdx.y;
    int j0 = tile * 32;
    int k0seg = seg * KSEG;

    int srow = tid >> 1;
    int sko = (tid & 1) * 16;
    int wrow = (srow >> 5) * HH + j0 + (srow & 31);   // gate-major row
    unsigned wdst0 = (unsigned)__cvta_generic_to_shared(&Ws[0][srow][sko]);
    unsigned wdst1 = (unsigned)__cvta_generic_to_shared(&Ws[1][srow][sko]);
    unsigned xdst0 = (unsigned)__cvta_generic_to_shared(&xs[0][0][0]) + tid * 16;
    unsigned xdst1 = (unsigned)__cvta_generic_to_shared(&xs[1][0][0]) + tid * 16;

    auto do_stage = [&](int buf, int c) {
        int kk = k0seg + c * KC;
        const float* wsrc;
        if (kk < EE) wsrc = Wih + (size_t)wrow * EE + kk + sko;
        else         wsrc = Whh + (size_t)wrow * HH + (kk - EE) + sko;
        unsigned wd = buf ? wdst1 : wdst0;
#pragma unroll
        for (int ch = 0; ch < 4; ch++)
            cp_async16(wd + ch * 16, wsrc + ch * 4);
        cp_async16(buf ? xdst1 : xdst0, xh_r + (size_t)kk * BB + tid * 4);
        cp_commit();
    };

    do_stage(0, 0);
    do_stage(1, 1);

    unsigned long long acc[4][2];
#pragma unroll
    for (int rj = 0; rj < 4; rj++) { acc[rj][0] = 0ull; acc[rj][1] = 0ull; }

    for (int c = 0; c < NCHUNK_LSTM; c++) {
        if (c == NCHUNK_LSTM - 1)
            asm volatile("cp.async.wait_group 0;" ::: "memory");
        else
            asm volatile("cp.async.wait_group 1;" ::: "memory");
        __syncthreads();
        int buf = c & 1;
#pragma unroll
        for (int k4 = 0; k4 < KC / 4; k4++) {
            unsigned long long h01[4], h23[4];
#pragma unroll
            for (int i = 0; i < 4; i++) {
                float4 h4 = *(const float4*)&xs[buf][k4 * 4 + i][bt * 4];
                h01[i] = pack2(h4.x, h4.y);
                h23[i] = pack2(h4.z, h4.w);
            }
#pragma unroll
            for (int rj = 0; rj < 4; rj++) {
                float4 w4 = *(const float4*)&Ws[buf][rt + 32 * rj][k4 * 4];
                unsigned long long w;
                w = pack2(w4.x, w4.x);
                acc[rj][0] = fma2(w, h01[0], acc[rj][0]);
                acc[rj][1] = fma2(w, h23[0], acc[rj][1]);
                w = pack2(w4.y, w4.y);
                acc[rj][0] = fma2(w, h01[1], acc[rj][0]);
                acc[rj][1] = fma2(w, h23[1], acc[rj][1]);
                w = pack2(w4.z, w4.z);
                acc[rj][0] = fma2(w, h01[2], acc[rj][0]);
                acc[rj][1] = fma2(w, h23[2], acc[rj][1]);
                w = pack2(w4.w, w4.w);
                acc[rj][0] = fma2(w, h01[3], acc[rj][0]);
                acc[rj][1] = fma2(w, h23[3], acc[rj][1]);
            }
        }
        __syncthreads();
        if (c + 2 < NCHUNK_LSTM) do_stage(buf, c + 2);
    }

    float vals[4][4];
#pragma unroll
    for (int rj = 0; rj < 4; rj++) {
        unpack2(acc[rj][0], vals[rj][0], vals[rj][1]);
        unpack2(acc[rj][1], vals[rj][2], vals[rj][3]);
    }
    float* ap = g_acc + (size_t)tile * 128 * BB;

    if (seg == 0) {
#pragma unroll
        for (int rj = 0; rj < 4; rj++) {
            float4 o = make_float4(vals[rj][0], vals[rj][1], vals[rj][2], vals[rj][3]);
            __stcg((float4*)&ap[(rt + 32 * rj) * BB + bt * 4], o);
        }
        __syncthreads();
        __threadfence();
        if (tid == 0) atomicExch(&g_cnt[tile], 1);
    } else {
        if (tid == 0) { while (atomicAdd(&g_cnt[tile], 0) != seg) { } }
        __syncthreads();
        __threadfence();
        if (seg < SPLITK - 1) {
#pragma unroll
            for (int rj = 0; rj < 4; rj++) {
                float4 o = __ldcg((const float4*)&ap[(rt + 32 * rj) * BB + bt * 4]);
                o.x += vals[rj][0]; o.y += vals[rj][1];
                o.z += vals[rj][2]; o.w += vals[rj][3];
                __stcg((float4*)&ap[(rt + 32 * rj) * BB + bt * 4], o);
            }
            __syncthreads();
            __threadfence();
            if (tid == 0) atomicExch(&g_cnt[tile], seg + 1);
        } else {
            // final segment: reduce + biases + cell, rj == gate
            int j = j0 + rt;
            float a[4][4];
#pragma unroll
            for (int g = 0; g < 4; g++) {
                float4 o = __ldcg((const float4*)&ap[(rt + 32 * g) * BB + bt * 4]);
                float bias = bih[g * HH + j] + bhh[g * HH + j];
                a[g][0] = o.x + vals[g][0] + bias;
                a[g][1] = o.y + vals[g][1] + bias;
                a[g][2] = o.z + vals[g][2] + bias;
                a[g][3] = o.w + vals[g][3] + bias;
            }
#pragma unroll
            for (int bi = 0; bi < 4; bi++) {
                int b = bt * 4 + bi;
                float ig = 1.0f / (1.0f + expf(-a[0][bi]));
                float fg = 1.0f / (1.0f + expf(-a[1][bi]));
                float gg = tanhf(a[2][bi]);
                float og = 1.0f / (1.0f + expf(-a[3][bi]));
                float c = fg * cbuf[j * BB + b] + ig * gg;
                float h = og * tanhf(c);
                cbuf[j * BB + b] = c;
                xh_w[(size_t)(EE + j) * BB + b] = h;
            }
            if (tid == 0) atomicExch(&g_cnt[tile], 0);  // reset for next step
        }
    }
}

// ---------------- K2: logits GEMM + gumbel + atomic argmax ----------------
__global__ __launch_bounds__(256, 3) void logits_kernel(
    const float* __restrict__ hT, const float* __restrict__ Wout,
    const float* __restrict__ bout, float* __restrict__ stage,
    unsigned long long* __restrict__ best, int t, unsigned key0, unsigned key1) {
    __shared__ __align__(16) float Ws[2][TILEV][WS_STRIDE];
    __shared__ __align__(16) float hs[2][KC][BB];
    int tid = threadIdx.x;
    int vt = tid & 31;
    int bt = tid >> 5;
    int v0 = blockIdx.x * TILEV;

    int srow = tid >> 1;
    int sko = (tid & 1) * 16;
    unsigned wdst0 = (unsigned)__cvta_generic_to_shared(&Ws[0][srow][sko]);
    unsigned wdst1 = (unsigned)__cvta_generic_to_shared(&Ws[1][srow][sko]);
    unsigned hdst0 = (unsigned)__cvta_generic_to_shared(&hs[0][0][0]) + tid * 16;
    unsigned hdst1 = (unsigned)__cvta_generic_to_shared(&hs[1][0][0]) + tid * 16;

    auto do_stage = [&](int buf, int c) {
        int kc = c * KC;
        const float* wsrc = Wout + (size_t)(v0 + srow) * HH + kc + sko;
        unsigned wd = buf ? wdst1 : wdst0;
#pragma unroll
        for (int ch = 0; ch < 4; ch++)
            cp_async16(wd + ch * 16, wsrc + ch * 4);
        cp_async16(buf ? hdst1 : hdst0, hT + (size_t)kc * BB + tid * 4);
        cp_commit();
    };

    do_stage(0, 0);
    do_stage(1, 1);

    unsigned long long acc[4][2];
#pragma unroll
    for (int vj = 0; vj < 4; vj++) { acc[vj][0] = 0ull; acc[vj][1] = 0ull; }

    for (int c = 0; c < NCHUNK_LOG; c++) {
        if (c == NCHUNK_LOG - 1)
            asm volatile("cp.async.wait_group 0;" ::: "memory");
        else
            asm volatile("cp.async.wait_group 1;" ::: "memory");
        __syncthreads();
        int buf = c & 1;
#pragma unroll
        for (int k4 = 0; k4 < KC / 4; k4++) {
            unsigned long long h01[4], h23[4];
#pragma unroll
            for (int i = 0; i < 4; i++) {
                float4 h4 = *(const float4*)&hs[buf][k4 * 4 + i][bt * 4];
                h01[i] = pack2(h4.x, h4.y);
                h23[i] = pack2(h4.z, h4.w);
            }
#pragma unroll
            for (int vj = 0; vj < 4; vj++) {
                float4 w4 = *(const float4*)&Ws[buf][vt + 32 * vj][k4 * 4];
                unsigned long long w;
                w = pack2(w4.x, w4.x);
                acc[vj][0] = fma2(w, h01[0], acc[vj][0]);
                acc[vj][1] = fma2(w, h23[0], acc[vj][1]);
                w = pack2(w4.y, w4.y);
                acc[vj][0] = fma2(w, h01[1], acc[vj][0]);
                acc[vj][1] = fma2(w, h23[1], acc[vj][1]);
                w = pack2(w4.z, w4.z);
                acc[vj][0] = fma2(w, h01[2], acc[vj][0]);
                acc[vj][1] = fma2(w, h23[2], acc[vj][1]);
                w = pack2(w4.w, w4.w);
                acc[vj][0] = fma2(w, h01[3], acc[vj][0]);
                acc[vj][1] = fma2(w, h23[3], acc[vj][1]);
            }
        }
        __syncthreads();
        if (c + 2 < NCHUNK_LOG) do_stage(buf, c + 2);
    }

    float lg[4][4];
#pragma unroll
    for (int vj = 0; vj < 4; vj++) {
        unpack2(acc[vj][0], lg[vj][0], lg[vj][1]);
        unpack2(acc[vj][1], lg[vj][2], lg[vj][3]);
        float bo = bout[v0 + vt + 32 * vj];
#pragma unroll
        for (int bi = 0; bi < 4; bi++) lg[vj][bi] += bo;
    }
#pragma unroll
    for (int bi = 0; bi < 4; bi++) {
        int b = bt * 4 + bi;
        float* sp = stage + ((size_t)b * TT + t) * VV + v0 + vt;
        unsigned long long bk = 0ull;
#pragma unroll
        for (int vj = 0; vj < 4; vj++) {
            int v = v0 + vt + 32 * vj;
            float logit = lg[vj][bi];
            sp[32 * vj] = logit;
            unsigned i = (unsigned)(b * VV + v);
            unsigned o0, o1;
            threefry2x32_dev(key0, key1, 0u, i, o0, o1);
            unsigned bits = o0 ^ o1;
            float u = __uint_as_float(0x3f800000u | (bits >> 9)) - 1.0f;
            u = fmaxf(u + F32_TINY, F32_TINY);
            float g = -logf(-logf(u));
            float val = logit + g;
            unsigned long long key =
                ((unsigned long long)ford(val) << 32) |
                (unsigned long long)(0xFFFFFFFFu - (unsigned)v);
            bk = u64max(bk, key);
        }
#pragma unroll
        for (int off = 1; off < 32; off <<= 1) {
            unsigned long long o = __shfl_xor_sync(0xffffffffu, bk, off);
            bk = u64max(bk, o);
        }
        if (vt == 0) atomicMax(&best[t * BB + b], bk);
    }
}

// ---------------- final: captions ----------------
__global__ void caption_kernel(float* __restrict__ cap_f, int* __restrict__ cap_i) {
    int idx = blockIdx.x * 256 + threadIdx.x;
    int tt = idx & 63;
    int b = idx >> 6;
    int v = decode_tok(g_best[tt * BB + b]);
    if (cap_f) cap_f[b * TT + tt] = (float)v;
    if (cap_i) cap_i[b * TT + tt] = v;
}

// ---------------- final: transpose staging [b][t][v] -> [b][v][t] --------
__global__ __launch_bounds__(256) void transpose_kernel(
    const float* __restrict__ stage, float* __restrict__ out) {
    __shared__ float tile[128][65];
    int b = blockIdx.x / 250;
    int vc = blockIdx.x % 250;
    int v0 = vc * 128;
    const float* src = stage + (size_t)b * TT * VV + v0;
#pragma unroll
    for (int l = 0; l < 32; l++) {
        int e = threadIdx.x + l * 256;
        int tt = e >> 7;
        int vi = e & 127;
        tile[vi][tt] = src[(size_t)tt * VV + vi];
    }
    __syncthreads();
    float* dst = out + ((size_t)b * VV + v0) * TT;
#pragma unroll
    for (int l = 0; l < 32; l++) {
        int e = threadIdx.x + l * 256;
        int vi = e >> 6;
        int tt = e & 63;
        dst[(size_t)vi * TT + tt] = tile[vi][tt];
    }
}

// ---------------- host threefry ----------------
static void host_threefry(unsigned k0, unsigned k1, unsigned x0, unsigned x1,
                          unsigned& o0, unsigned& o1) {
    unsigned ks2 = k0 ^ k1 ^ 0x1BD11BDAu;
    x0 += k0; x1 += k1;
#define HTF_RND(r) { x0 += x1; x1 = (x1 << r) | (x1 >> (32 - r)); x1 ^= x0; }
    HTF_RND(13) HTF_RND(15) HTF_RND(26) HTF_RND(6)  x0 += k1;  x1 += ks2 + 1u;
    HTF_RND(17) HTF_RND(29) HTF_RND(16) HTF_RND(24) x0 += ks2; x1 += k0 + 2u;
    HTF_RND(13) HTF_RND(15) HTF_RND(26) HTF_RND(6)  x0 += k0;  x1 += k1 + 3u;
    HTF_RND(17) HTF_RND(29) HTF_RND(16) HTF_RND(24) x0 += k1;  x1 += ks2 + 4u;
    HTF_RND(13) HTF_RND(15) HTF_RND(26) HTF_RND(6)  x0 += ks2; x1 += k0 + 5u;
#undef HTF_RND
    o0 = x0; o1 = x1;
}

extern "C" void kernel_launch(void* const* d_in, const int* in_sizes, int n_in,
                              void* d_out, int out_size) {
    const float* condition = (const float*)d_in[0];
    const float* Wh    = (const float*)d_in[1];
    const float* bh    = (const float*)d_in[2];
    const float* Wc    = (const float*)d_in[3];
    const float* bc    = (const float*)d_in[4];
    const float* embed = (const float*)d_in[5];
    const float* Wih   = (const float*)d_in[6];
    const float* bih   = (const float*)d_in[7];
    const float* Whh   = (const float*)d_in[8];
    const float* bhh   = (const float*)d_in[9];
    const float* Wout  = (const float*)d_in[10];
    const float* bout  = (const float*)d_in[11];

    float *xhA, *xhB, *cbuf, *stage;
    unsigned long long* best;
    cudaGetSymbolAddress((void**)&xhA, g_xhA);
    cudaGetSymbolAddress((void**)&xhB, g_xhB);
    cudaGetSymbolAddress((void**)&cbuf, g_c);
    cudaGetSymbolAddress((void**)&stage, g_stage);
    cudaGetSymbolAddress((void**)&best, g_best);

    const long long n_cap = (long long)BB * TT;
    const long long n_log = (long long)BB * VV * TT;
    float* cap_f = nullptr;
    int*   cap_i = nullptr;
    float* log_out = nullptr;
    long long osz = (long long)out_size;
    if (osz == n_cap + n_log) {
        cap_f = (float*)d_out;
        log_out = (float*)d_out + n_cap;
    } else if (osz == n_log) {
        log_out = (float*)d_out;
    } else if (osz == n_cap) {
        cap_i = (int*)d_out;
    } else {
        cap_f = (float*)d_out;
        log_out = (float*)d_out + n_cap;
    }

    // init: h0 -> xhA h-region, c0 -> g_c
    init_kernel<<<128, 256>>>(condition, Wh, bh, Wc, bc,
                              xhA + (size_t)EE * BB, cbuf);

    for (int t = 0; t < TT; t++) {
        float* xr = (t & 1) ? xhB : xhA;   // read: x (this step) + h (prev)
        float* xw = (t & 1) ? xhA : xhB;   // write: new h
        gather_kernel<<<64, 256>>>(embed, xr, t);
        dim3 ggrid(NTILE, SPLITK);
        lstm_kernel<<<ggrid, 256>>>(Wih, Whh, bih, bhh, xr, xw, cbuf);
        unsigned o0, o1;
        host_threefry(0u, 42u, 0u, (unsigned)t, o0, o1);
        logits_kernel<<<250, 256>>>(xw + (size_t)EE * BB, Wout, bout,
                                    stage, best, t, o0, o1);
    }
    caption_kernel<<<8, 256>>>(cap_f, cap_i);
    if (log_out) transpose_kernel<<<8000, 256>>>(stage, log_out);
}